// round 8
// baseline (speedup 1.0000x reference)
#include <cuda_runtime.h>
#include <cuda_fp16.h>

#define NN 40000
#define EE 640000
#define HD 128
#define GG 64
#define PADH 136   // padded halves per smem row (conflict-free ldmatrix)

// ---------------- scratch (no allocs: __device__ globals) -------------------
__device__ __align__(16) float  g_xw  [(size_t)NN * HD];   // x@W f32
__device__ __align__(16) __half g_xwh [(size_t)NN * HD];   // x@W fp16 (gather)
__device__ __align__(16) float  g_h   [(size_t)NN * HD];   // layer output f32
__device__ __align__(16) int    g_degi[NN];
__device__ __align__(16) float  g_dinv[NN];
__device__ __align__(16) int    g_dst [EE];
__device__ __align__(16) int    g_adj [EE];                // CSR: src grouped by dst
__device__ __align__(16) int    g_rowstart[NN + 1];
__device__ __align__(16) int    g_cursor[NN];
__device__ __align__(16) int    g_gstart[GG + 1];
__device__ __align__(16) float  g_pool[GG * HD];
__device__ int g_is64;

__device__ __forceinline__ int IDX(const void* p, long long pos) {
    return g_is64 ? (int)((const long long*)p)[pos] : ((const int*)p)[pos];
}

// ---------------- dtype detection (reads first 32KB only) -------------------
__global__ void detect_kernel(const unsigned int* __restrict__ raw) {
    __shared__ int nz;
    if (threadIdx.x == 0) nz = 0;
    __syncthreads();
    int cnt = 0;
    for (int j = threadIdx.x; j < 4096; j += 256)
        if (raw[2 * j + 1] != 0u) cnt++;
    atomicAdd(&nz, cnt);
    __syncthreads();
    if (threadIdx.x == 0) g_is64 = (nz < 64) ? 1 : 0;
}

// ---------------- prep ------------------------------------------------------
__global__ void zero_misc_kernel() {
    int i = blockIdx.x * blockDim.x + threadIdx.x;
    if (i < NN) { g_degi[i] = 0; g_cursor[i] = 0; }
    if (i <= GG) g_gstart[i] = NN;
    if (i < GG * HD) g_pool[i] = 0.f;
}

// index convert (src kept in g_adj staging? no: src stored to g_dst pass) -----
// conv: read both rows; store src temporarily in g_adj (overwritten by scatter
// later? no — scatter needs src. Keep src in its own pass: store src in g_dst
// staging is wrong. We store src in g_adj only AFTER scatter slots known.)
// So: keep src in registers is impossible across kernels -> store src in g_dst? 
// We need dst for scatter too. Use two arrays: g_dst (dst) and reuse g_adj as
// src staging until scatter reads it and writes final adjacency into... same
// array would race. Solution: scatter reads src from staging g_srcstage = g_xw
// memory? Simpler: keep a dedicated src array.
__device__ __align__(16) int g_srcs[EE];

__global__ void conv_deg_kernel(const void* __restrict__ ei) {
    int i = blockIdx.x * blockDim.x + threadIdx.x;
    if (i >= EE) return;
    int s = IDX(ei, i);
    int d = IDX(ei, (long long)EE + i);
    g_srcs[i] = s;
    g_dst[i] = d;
    atomicAdd(&g_degi[d], 1);
}

// single-block exclusive prefix sum over g_degi -> g_rowstart
__global__ __launch_bounds__(1024) void prefix_kernel() {
    int t = threadIdx.x;
    int base = t * 40;                 // 1024*40 >= 40000
    int s = 0;
    for (int j = 0; j < 40; j++) {
        int idx = base + j;
        if (idx < NN) s += g_degi[idx];
    }
    int lane = t & 31, wid = t >> 5;
    int v = s;
#pragma unroll
    for (int o = 1; o < 32; o <<= 1) {
        int u = __shfl_up_sync(~0u, v, o);
        if (lane >= o) v += u;
    }
    __shared__ int ws[32];
    if (lane == 31) ws[wid] = v;
    __syncthreads();
    if (wid == 0) {
        int w = ws[lane];
#pragma unroll
        for (int o = 1; o < 32; o <<= 1) {
            int u = __shfl_up_sync(~0u, w, o);
            if (lane >= o) w += u;
        }
        ws[lane] = w;
    }
    __syncthreads();
    int run = v - s + (wid ? ws[wid - 1] : 0);
    for (int j = 0; j < 40; j++) {
        int idx = base + j;
        if (idx < NN) { g_rowstart[idx] = run; run += g_degi[idx]; }
    }
    if (t == 0) g_rowstart[NN] = EE;
}

__global__ void dinv_kernel() {
    int i = blockIdx.x * blockDim.x + threadIdx.x;
    if (i < NN) g_dinv[i] = rsqrtf((float)g_degi[i] + 1.0f);
}

// graph boundaries from sorted batch (no atomics)
__global__ void gstart_kernel(const void* __restrict__ batch) {
    int i = blockIdx.x * blockDim.x + threadIdx.x;
    if (i >= NN) return;
    int b  = IDX(batch, i);
    int bp = i ? IDX(batch, i - 1) : -1;
    for (int g = bp + 1; g <= b; g++) g_gstart[g] = i;
}

// scatter edges into CSR slots
__global__ void scatter_kernel() {
    int i = blockIdx.x * blockDim.x + threadIdx.x;
    if (i >= EE) return;
    int d = g_dst[i];
    int pos = g_rowstart[d] + atomicAdd(&g_cursor[d], 1);
    g_adj[pos] = g_srcs[i];
}

// ---------------- tensor-core GEMM: C[M,128] = A[M,128] @ W[128,128] --------
__global__ __launch_bounds__(256) void gemm_tc_kernel(const float* __restrict__ A,
                                                      const float* __restrict__ W) {
    extern __shared__ __half smh[];
    __half* As = smh;                 // [128][PADH]
    __half* Bs = smh + 128 * PADH;    // [128][PADH]  (Bs[k][n])

    int tid = threadIdx.x;
    long long mbase = (long long)blockIdx.x * 128;

#pragma unroll
    for (int i = 0; i < 16; i++) {
        int idx = i * 256 + tid;
        int row = idx >> 5, c4 = idx & 31;
        long long grow = mbase + row;
        float4 v = (grow < NN) ? ((const float4*)A)[grow * 32 + c4]
                               : make_float4(0.f, 0.f, 0.f, 0.f);
        __half2* dst = (__half2*)(As + row * PADH + c4 * 4);
        dst[0] = __floats2half2_rn(v.x, v.y);
        dst[1] = __floats2half2_rn(v.z, v.w);
    }
#pragma unroll
    for (int i = 0; i < 16; i++) {
        int idx = i * 256 + tid;
        int row = idx >> 5, c4 = idx & 31;
        float4 v = ((const float4*)W)[row * 32 + c4];
        __half2* dst = (__half2*)(Bs + row * PADH + c4 * 4);
        dst[0] = __floats2half2_rn(v.x, v.y);
        dst[1] = __floats2half2_rn(v.z, v.w);
    }
    __syncthreads();

    int wid = tid >> 5, lane = tid & 31;
    int wm = (wid & 3) * 32;
    int wn = (wid >> 2) * 64;

    float acc[2][8][4];
#pragma unroll
    for (int mt = 0; mt < 2; mt++)
#pragma unroll
        for (int nt = 0; nt < 8; nt++)
#pragma unroll
            for (int q = 0; q < 4; q++) acc[mt][nt][q] = 0.f;

#pragma unroll
    for (int kk = 0; kk < 8; kk++) {
        unsigned a[2][4];
#pragma unroll
        for (int mt = 0; mt < 2; mt++) {
            int r = lane & 15, c = (lane >> 4) * 8;
            unsigned addr = (unsigned)__cvta_generic_to_shared(
                As + (wm + mt * 16 + r) * PADH + kk * 16 + c);
            asm volatile("ldmatrix.sync.aligned.m8n8.x4.shared.b16 {%0,%1,%2,%3}, [%4];"
                         : "=r"(a[mt][0]), "=r"(a[mt][1]), "=r"(a[mt][2]), "=r"(a[mt][3])
                         : "r"(addr));
        }
        unsigned b[8][2];
#pragma unroll
        for (int nt2 = 0; nt2 < 4; nt2++) {
            int krow = kk * 16 + ((lane >> 3) & 1) * 8 + (lane & 7);
            int ncol = wn + nt2 * 16 + (lane >> 4) * 8;
            unsigned addr = (unsigned)__cvta_generic_to_shared(Bs + krow * PADH + ncol);
            asm volatile("ldmatrix.sync.aligned.m8n8.x4.trans.shared.b16 {%0,%1,%2,%3}, [%4];"
                         : "=r"(b[nt2 * 2][0]), "=r"(b[nt2 * 2][1]),
                           "=r"(b[nt2 * 2 + 1][0]), "=r"(b[nt2 * 2 + 1][1])
                         : "r"(addr));
        }
#pragma unroll
        for (int mt = 0; mt < 2; mt++)
#pragma unroll
            for (int nt = 0; nt < 8; nt++)
                asm volatile("mma.sync.aligned.m16n8k16.row.col.f32.f16.f16.f32 "
                             "{%0,%1,%2,%3}, {%4,%5,%6,%7}, {%8,%9}, {%0,%1,%2,%3};"
                             : "+f"(acc[mt][nt][0]), "+f"(acc[mt][nt][1]),
                               "+f"(acc[mt][nt][2]), "+f"(acc[mt][nt][3])
                             : "r"(a[mt][0]), "r"(a[mt][1]), "r"(a[mt][2]), "r"(a[mt][3]),
                               "r"(b[nt][0]), "r"(b[nt][1]));
    }

    int r0 = lane >> 2, cq = (lane & 3) * 2;
#pragma unroll
    for (int mt = 0; mt < 2; mt++) {
        long long rowA = mbase + wm + mt * 16 + r0;
        long long rowB = rowA + 8;
#pragma unroll
        for (int nt = 0; nt < 8; nt++) {
            int col = wn + nt * 8 + cq;
            if (rowA < NN) {
                *(float2*)&g_xw[rowA * HD + col] = make_float2(acc[mt][nt][0], acc[mt][nt][1]);
                *(__half2*)&g_xwh[rowA * HD + col] = __floats2half2_rn(acc[mt][nt][0], acc[mt][nt][1]);
            }
            if (rowB < NN) {
                *(float2*)&g_xw[rowB * HD + col] = make_float2(acc[mt][nt][2], acc[mt][nt][3]);
                *(__half2*)&g_xwh[rowB * HD + col] = __floats2half2_rn(acc[mt][nt][2], acc[mt][nt][3]);
            }
        }
    }
}

// ---------------- warp-per-node CSR aggregation + fused epilogue ------------
// Adjacency + dinv batched per 32 edges, broadcast via shuffle; per edge each
// lane gathers 8B of the src row; f32 register accumulate; one store per node.
__device__ __forceinline__ void acc_edge(float* acc, unsigned lo, unsigned hi, float nm) {
    float2 f0 = __half22float2(*(__half2*)&lo);
    float2 f1 = __half22float2(*(__half2*)&hi);
    acc[0] = fmaf(f0.x, nm, acc[0]);
    acc[1] = fmaf(f0.y, nm, acc[1]);
    acc[2] = fmaf(f1.x, nm, acc[2]);
    acc[3] = fmaf(f1.y, nm, acc[3]);
}

__global__ __launch_bounds__(256) void agg_kernel(const float* __restrict__ b) {
    int n = blockIdx.x * 8 + (threadIdx.x >> 5);   // 5000 blocks * 8 warps = NN
    int lane = threadIdx.x & 31;
    int beg = g_rowstart[n], end = g_rowstart[n + 1];
    float dn = g_dinv[n];

    float acc[4] = {0.f, 0.f, 0.f, 0.f};
    const uint2* xh = (const uint2*)g_xwh;         // 32 uint2 per row

    for (int base = beg; base < end; base += 32) {
        int m = end - base;
        int cnt = m < 32 ? m : 32;
        int a = (lane < cnt) ? g_adj[base + lane] : 0;
        float nml = (lane < cnt) ? dn * g_dinv[a] : 0.f;

        int e = 0;
        for (; e + 4 <= cnt; e += 4) {
            int s0 = __shfl_sync(~0u, a, e);
            int s1 = __shfl_sync(~0u, a, e + 1);
            int s2 = __shfl_sync(~0u, a, e + 2);
            int s3 = __shfl_sync(~0u, a, e + 3);
            float n0 = __shfl_sync(~0u, nml, e);
            float n1 = __shfl_sync(~0u, nml, e + 1);
            float n2 = __shfl_sync(~0u, nml, e + 2);
            float n3 = __shfl_sync(~0u, nml, e + 3);
            uint2 v0 = xh[(size_t)s0 * 32 + lane];
            uint2 v1 = xh[(size_t)s1 * 32 + lane];
            uint2 v2 = xh[(size_t)s2 * 32 + lane];
            uint2 v3 = xh[(size_t)s3 * 32 + lane];
            acc_edge(acc, v0.x, v0.y, n0);
            acc_edge(acc, v1.x, v1.y, n1);
            acc_edge(acc, v2.x, v2.y, n2);
            acc_edge(acc, v3.x, v3.y, n3);
        }
        for (; e < cnt; e++) {
            int s0 = __shfl_sync(~0u, a, e);
            float n0 = __shfl_sync(~0u, nml, e);
            uint2 v0 = xh[(size_t)s0 * 32 + lane];
            acc_edge(acc, v0.x, v0.y, n0);
        }
    }

    // epilogue: h = relu(acc + xw*dinv^2 + b); lane owns cols [4*lane, 4*lane+4)
    float dd = dn * dn;
    float4 w  = ((const float4*)(g_xw + (size_t)n * HD))[lane];
    float4 bb = ((const float4*)b)[lane];
    float4 h;
    h.x = fmaxf(fmaf(w.x, dd, acc[0]) + bb.x, 0.f);
    h.y = fmaxf(fmaf(w.y, dd, acc[1]) + bb.y, 0.f);
    h.z = fmaxf(fmaf(w.z, dd, acc[2]) + bb.z, 0.f);
    h.w = fmaxf(fmaf(w.w, dd, acc[3]) + bb.w, 0.f);
    ((float4*)(g_h + (size_t)n * HD))[lane] = h;
}

// ---------------- mean pool: segmented accumulation (sorted batch) ----------
#define PB 250
#define PNODES 160          // 250 * 160 = 40000
__global__ __launch_bounds__(128) void pool_accum_kernel(const void* __restrict__ batch) {
    int t = threadIdx.x;
    int s = blockIdx.x * PNODES, e = s + PNODES;
    float acc = 0.f;
    int gcur = IDX(batch, s);
    for (int n = s; n < e; n++) {
        int g = IDX(batch, n);
        if (g != gcur) {
            atomicAdd(&g_pool[gcur * HD + t], acc);
            acc = 0.f;
            gcur = g;
        }
        acc += g_h[(size_t)n * HD + t];
    }
    atomicAdd(&g_pool[gcur * HD + t], acc);
}

__global__ void pool_final_kernel(float* __restrict__ out) {
    int i = blockIdx.x * blockDim.x + threadIdx.x;
    if (i >= GG * HD) return;
    int g = i >> 7;
    float c = (float)(g_gstart[g + 1] - g_gstart[g]);
    out[i] = g_pool[i] / fmaxf(c, 1.0f);
}

// ---------------- launch -----------------------------------------------------
extern "C" void kernel_launch(void* const* d_in, const int* in_sizes, int n_in,
                              void* d_out, int out_size) {
    const float *x = 0, *W1 = 0, *b1 = 0, *W2 = 0, *b2 = 0;
    const void  *ei = 0, *batch = 0;
    for (int i = 0; i < n_in; i++) {
        long long sz = in_sizes[i];
        if      (sz == (long long)NN * HD) x = (const float*)d_in[i];
        else if (sz == 2LL * EE)           ei = d_in[i];
        else if (sz == NN)                 batch = d_in[i];
        else if (sz == HD * HD) { if (!W1) W1 = (const float*)d_in[i];
                                  else     W2 = (const float*)d_in[i]; }
        else if (sz == HD)      { if (!b1) b1 = (const float*)d_in[i];
                                  else     b2 = (const float*)d_in[i]; }
    }
    float* out = (float*)d_out;

    static cudaStream_t sA = 0;
    static cudaEvent_t ev0 = 0, ev1 = 0;
    static void* h_addr = 0;
    if (!sA) {
        cudaStreamCreateWithFlags(&sA, cudaStreamNonBlocking);
        cudaEventCreateWithFlags(&ev0, cudaEventDisableTiming);
        cudaEventCreateWithFlags(&ev1, cudaEventDisableTiming);
        cudaGetSymbolAddress(&h_addr, g_h);
        cudaFuncSetAttribute((const void*)gemm_tc_kernel,
                             cudaFuncAttributeMaxDynamicSharedMemorySize,
                             2 * 128 * PADH * (int)sizeof(__half));
    }

    const int ZB    = (GG * HD + 255) / 256;  // 32 covers NN? no: use max
    const int ZBM   = (NN + 255) / 256;       // 157 (covers all zero_misc ranges)
    const int EB    = (EE + 255) / 256;       // 2500
    const int GEMMB = (NN + 127) / 128;       // 313
    const int GSM   = 2 * 128 * PADH * (int)sizeof(__half);
    (void)ZB;

    // fork: GEMM1 on sA; CSR build chain on main stream
    cudaEventRecord(ev0, 0);
    cudaStreamWaitEvent(sA, ev0, 0);
    gemm_tc_kernel<<<GEMMB, 256, GSM, sA>>>(x, W1);
    cudaEventRecord(ev1, sA);

    detect_kernel<<<1, 256>>>((const unsigned int*)ei);
    zero_misc_kernel<<<ZBM, 256>>>();
    conv_deg_kernel<<<EB, 256>>>(ei);
    prefix_kernel<<<1, 1024>>>();
    dinv_kernel<<<ZBM, 256>>>();
    gstart_kernel<<<ZBM, 256>>>(batch);
    scatter_kernel<<<EB, 256>>>();

    // join: layer 1
    cudaStreamWaitEvent(0, ev1, 0);
    agg_kernel<<<NN / 8, 256>>>(b1);

    // layer 2 (serial dependency through g_h)
    gemm_tc_kernel<<<GEMMB, 256, GSM>>>((const float*)h_addr, W2);
    agg_kernel<<<NN / 8, 256>>>(b2);

    // pool
    pool_accum_kernel<<<PB, 128>>>(batch);
    pool_final_kernel<<<(GG * HD + 255) / 256, 256>>>(out);
}

// round 9
// speedup vs baseline: 1.0470x; 1.0470x over previous
#include <cuda_runtime.h>
#include <cuda_fp16.h>

#define NN 40000
#define EE 640000
#define HD 128
#define GG 64
#define PADH 136   // padded halves per smem row (conflict-free ldmatrix)

// ---------------- scratch (no allocs: __device__ globals) -------------------
__device__ __align__(16) float  g_xw  [(size_t)NN * HD];   // x@W f32
__device__ __align__(16) __half g_xwh [(size_t)NN * HD];   // x@W fp16 (gather)
__device__ __align__(16) __half g_aggh[(size_t)NN * HD];   // fp16 edge accum
__device__ __align__(16) float  g_h   [(size_t)NN * HD];   // layer output f32
__device__ __align__(16) int    g_degi[NN];
__device__ __align__(16) float  g_dinv[NN];
__device__ __align__(16) int2   g_edge[EE];                // packed (src, dst)
__device__ __align__(16) float  g_norm[EE];                // dinv[s]*dinv[d]
__device__ __align__(16) int    g_gstart[GG + 1];
__device__ __align__(16) float  g_pool[GG * HD];
__device__ int g_is64;

__device__ __forceinline__ int IDX(const void* p, long long pos) {
    return g_is64 ? (int)((const long long*)p)[pos] : ((const int*)p)[pos];
}

// ---------------- dtype detection (reads first 32KB only) -------------------
__global__ void detect_kernel(const unsigned int* __restrict__ raw) {
    __shared__ int nz;
    if (threadIdx.x == 0) nz = 0;
    __syncthreads();
    int cnt = 0;
    for (int j = threadIdx.x; j < 4096; j += 256)
        if (raw[2 * j + 1] != 0u) cnt++;
    atomicAdd(&nz, cnt);
    __syncthreads();
    if (threadIdx.x == 0) g_is64 = (nz < 64) ? 1 : 0;
}

// ---------------- prep ------------------------------------------------------
__global__ void zero_misc_kernel() {
    int i = blockIdx.x * blockDim.x + threadIdx.x;
    if (i < NN) g_degi[i] = 0;
    if (i <= GG) g_gstart[i] = NN;
    if (i < GG * HD) g_pool[i] = 0.f;
}

// index convert + in-degree histogram (no 64-bin count atomics)
__global__ void conv_deg_kernel(const void* __restrict__ ei) {
    int i = blockIdx.x * blockDim.x + threadIdx.x;
    if (i >= EE) return;
    int s = IDX(ei, i);
    int d = IDX(ei, (long long)EE + i);
    g_edge[i] = make_int2(s, d);
    atomicAdd(&g_degi[d], 1);
}

__global__ void dinv_kernel() {
    int i = blockIdx.x * blockDim.x + threadIdx.x;
    if (i < NN) g_dinv[i] = rsqrtf((float)g_degi[i] + 1.0f);
}

// graph boundaries from sorted batch (no atomics)
__global__ void gstart_kernel(const void* __restrict__ batch) {
    int i = blockIdx.x * blockDim.x + threadIdx.x;
    if (i >= NN) return;
    int b  = IDX(batch, i);
    int bp = i ? IDX(batch, i - 1) : -1;
    for (int g = bp + 1; g <= b; g++) g_gstart[g] = i;
}

// per-edge normalization coefficient
__global__ void norm_kernel() {
    int i = blockIdx.x * blockDim.x + threadIdx.x;
    if (i >= EE) return;
    int2 sd = g_edge[i];
    g_norm[i] = __ldg(&g_dinv[sd.x]) * __ldg(&g_dinv[sd.y]);
}

// ---------------- tensor-core GEMM: C[M,128] = A[M,128] @ W[128,128] --------
__global__ __launch_bounds__(256) void gemm_tc_kernel(const float* __restrict__ A,
                                                      const float* __restrict__ W) {
    extern __shared__ __half smh[];
    __half* As = smh;                 // [128][PADH]
    __half* Bs = smh + 128 * PADH;    // [128][PADH]  (Bs[k][n])

    int tid = threadIdx.x;
    long long mbase = (long long)blockIdx.x * 128;

#pragma unroll
    for (int i = 0; i < 16; i++) {
        int idx = i * 256 + tid;
        int row = idx >> 5, c4 = idx & 31;
        long long grow = mbase + row;
        float4 v = (grow < NN) ? ((const float4*)A)[grow * 32 + c4]
                               : make_float4(0.f, 0.f, 0.f, 0.f);
        __half2* dst = (__half2*)(As + row * PADH + c4 * 4);
        dst[0] = __floats2half2_rn(v.x, v.y);
        dst[1] = __floats2half2_rn(v.z, v.w);
    }
#pragma unroll
    for (int i = 0; i < 16; i++) {
        int idx = i * 256 + tid;
        int row = idx >> 5, c4 = idx & 31;
        float4 v = ((const float4*)W)[row * 32 + c4];
        __half2* dst = (__half2*)(Bs + row * PADH + c4 * 4);
        dst[0] = __floats2half2_rn(v.x, v.y);
        dst[1] = __floats2half2_rn(v.z, v.w);
    }
    __syncthreads();

    int wid = tid >> 5, lane = tid & 31;
    int wm = (wid & 3) * 32;
    int wn = (wid >> 2) * 64;

    float acc[2][8][4];
#pragma unroll
    for (int mt = 0; mt < 2; mt++)
#pragma unroll
        for (int nt = 0; nt < 8; nt++)
#pragma unroll
            for (int q = 0; q < 4; q++) acc[mt][nt][q] = 0.f;

#pragma unroll
    for (int kk = 0; kk < 8; kk++) {
        unsigned a[2][4];
#pragma unroll
        for (int mt = 0; mt < 2; mt++) {
            int r = lane & 15, c = (lane >> 4) * 8;
            unsigned addr = (unsigned)__cvta_generic_to_shared(
                As + (wm + mt * 16 + r) * PADH + kk * 16 + c);
            asm volatile("ldmatrix.sync.aligned.m8n8.x4.shared.b16 {%0,%1,%2,%3}, [%4];"
                         : "=r"(a[mt][0]), "=r"(a[mt][1]), "=r"(a[mt][2]), "=r"(a[mt][3])
                         : "r"(addr));
        }
        unsigned b[8][2];
#pragma unroll
        for (int nt2 = 0; nt2 < 4; nt2++) {
            int krow = kk * 16 + ((lane >> 3) & 1) * 8 + (lane & 7);
            int ncol = wn + nt2 * 16 + (lane >> 4) * 8;
            unsigned addr = (unsigned)__cvta_generic_to_shared(Bs + krow * PADH + ncol);
            asm volatile("ldmatrix.sync.aligned.m8n8.x4.trans.shared.b16 {%0,%1,%2,%3}, [%4];"
                         : "=r"(b[nt2 * 2][0]), "=r"(b[nt2 * 2][1]),
                           "=r"(b[nt2 * 2 + 1][0]), "=r"(b[nt2 * 2 + 1][1])
                         : "r"(addr));
        }
#pragma unroll
        for (int mt = 0; mt < 2; mt++)
#pragma unroll
            for (int nt = 0; nt < 8; nt++)
                asm volatile("mma.sync.aligned.m16n8k16.row.col.f32.f16.f16.f32 "
                             "{%0,%1,%2,%3}, {%4,%5,%6,%7}, {%8,%9}, {%0,%1,%2,%3};"
                             : "+f"(acc[mt][nt][0]), "+f"(acc[mt][nt][1]),
                               "+f"(acc[mt][nt][2]), "+f"(acc[mt][nt][3])
                             : "r"(a[mt][0]), "r"(a[mt][1]), "r"(a[mt][2]), "r"(a[mt][3]),
                               "r"(b[nt][0]), "r"(b[nt][1]));
    }

    int r0 = lane >> 2, cq = (lane & 3) * 2;
#pragma unroll
    for (int mt = 0; mt < 2; mt++) {
        long long rowA = mbase + wm + mt * 16 + r0;
        long long rowB = rowA + 8;
#pragma unroll
        for (int nt = 0; nt < 8; nt++) {
            int col = wn + nt * 8 + cq;
            if (rowA < NN) {
                *(float2*)&g_xw[rowA * HD + col] = make_float2(acc[mt][nt][0], acc[mt][nt][1]);
                *(__half2*)&g_xwh[rowA * HD + col] = __floats2half2_rn(acc[mt][nt][0], acc[mt][nt][1]);
            }
            if (rowB < NN) {
                *(float2*)&g_xw[rowB * HD + col] = make_float2(acc[mt][nt][2], acc[mt][nt][3]);
                *(__half2*)&g_xwh[rowB * HD + col] = __floats2half2_rn(acc[mt][nt][2], acc[mt][nt][3]);
            }
        }
    }
}

// ---------------- edge scatter: aggh[dst] += xwh[src] * norm (3 LD + 1 RED) -
__global__ __launch_bounds__(256) void edge_kernel() {
    long long t = (long long)blockIdx.x * 256 + threadIdx.x;
    int e = (int)(t >> 4);
    if (e >= EE) return;
    int sub = threadIdx.x & 15;
    int2 sd = g_edge[e];
    float nm = g_norm[e];
    uint4 v = ((const uint4*)g_xwh)[(size_t)sd.x * 16 + sub];
    __half2* hv = (__half2*)&v;
#pragma unroll
    for (int i = 0; i < 4; i++) {
        float2 f = __half22float2(hv[i]);
        hv[i] = __floats2half2_rn(f.x * nm, f.y * nm);
    }
    __half* p = g_aggh + (size_t)sd.y * HD + sub * 8;
    asm volatile("red.global.add.noftz.v4.f16x2 [%0], {%1,%2,%3,%4};"
                 :: "l"(p), "r"(v.x), "r"(v.y), "r"(v.z), "r"(v.w)
                 : "memory");
}

// ---------------- node epilogue: h = relu(aggh + xw*dinv^2 + b) -------------
__global__ void node_kernel(const float* __restrict__ b) {
    int i = blockIdx.x * blockDim.x + threadIdx.x;   // over NN*32 float4s
    int node = i >> 5, q = i & 31;
    float di = g_dinv[node];
    float d2 = di * di;
    uint2 av = ((const uint2*)g_aggh)[i];
    float2 a0 = __half22float2(*(__half2*)&av.x);
    float2 a1 = __half22float2(*(__half2*)&av.y);
    float4 w  = ((const float4*)g_xw)[i];
    float4 bb = ((const float4*)b)[q];
    float4 h;
    h.x = fmaxf(fmaf(w.x, d2, a0.x) + bb.x, 0.f);
    h.y = fmaxf(fmaf(w.y, d2, a0.y) + bb.y, 0.f);
    h.z = fmaxf(fmaf(w.z, d2, a1.x) + bb.z, 0.f);
    h.w = fmaxf(fmaf(w.w, d2, a1.y) + bb.w, 0.f);
    ((float4*)g_h)[i] = h;
}

// ---------------- mean pool: register-segmented over sorted batch -----------
#define PB 250
#define PNODES 160          // 250 * 160 = 40000
__global__ __launch_bounds__(128) void pool_accum_kernel(const void* __restrict__ batch) {
    int t = threadIdx.x;
    int s = blockIdx.x * PNODES, e = s + PNODES;
    float acc = 0.f;
    int gcur = IDX(batch, s);
    for (int n = s; n < e; n++) {
        int g = IDX(batch, n);
        if (g != gcur) {
            atomicAdd(&g_pool[gcur * HD + t], acc);
            acc = 0.f;
            gcur = g;
        }
        acc += g_h[(size_t)n * HD + t];
    }
    atomicAdd(&g_pool[gcur * HD + t], acc);
}

__global__ void pool_final_kernel(float* __restrict__ out) {
    int i = blockIdx.x * blockDim.x + threadIdx.x;
    if (i >= GG * HD) return;
    int g = i >> 7;
    float c = (float)(g_gstart[g + 1] - g_gstart[g]);
    out[i] = g_pool[i] / fmaxf(c, 1.0f);
}

// ---------------- launch -----------------------------------------------------
extern "C" void kernel_launch(void* const* d_in, const int* in_sizes, int n_in,
                              void* d_out, int out_size) {
    const float *x = 0, *W1 = 0, *b1 = 0, *W2 = 0, *b2 = 0;
    const void  *ei = 0, *batch = 0;
    for (int i = 0; i < n_in; i++) {
        long long sz = in_sizes[i];
        if      (sz == (long long)NN * HD) x = (const float*)d_in[i];
        else if (sz == 2LL * EE)           ei = d_in[i];
        else if (sz == NN)                 batch = d_in[i];
        else if (sz == HD * HD) { if (!W1) W1 = (const float*)d_in[i];
                                  else     W2 = (const float*)d_in[i]; }
        else if (sz == HD)      { if (!b1) b1 = (const float*)d_in[i];
                                  else     b2 = (const float*)d_in[i]; }
    }
    float* out = (float*)d_out;

    static cudaStream_t sA = 0;
    static cudaEvent_t ev0 = 0, ev1 = 0, ev2 = 0, ev3 = 0;
    static void* aggh_addr = 0;
    static void* h_addr = 0;
    if (!sA) {
        cudaStreamCreateWithFlags(&sA, cudaStreamNonBlocking);
        cudaEventCreateWithFlags(&ev0, cudaEventDisableTiming);
        cudaEventCreateWithFlags(&ev1, cudaEventDisableTiming);
        cudaEventCreateWithFlags(&ev2, cudaEventDisableTiming);
        cudaEventCreateWithFlags(&ev3, cudaEventDisableTiming);
        cudaGetSymbolAddress(&aggh_addr, g_aggh);
        cudaGetSymbolAddress(&h_addr, g_h);
        cudaFuncSetAttribute((const void*)gemm_tc_kernel,
                             cudaFuncAttributeMaxDynamicSharedMemorySize,
                             2 * 128 * PADH * (int)sizeof(__half));
    }

    const int ZBM   = (NN + 255) / 256;       // 157
    const int EB    = (EE + 255) / 256;       // 2500
    const int EDGB  = (EE * 16) / 256;        // 40000
    const int NODB  = (NN * 32) / 256;        // 5000
    const int GEMMB = (NN + 127) / 128;       // 313
    const int GSM   = 2 * 128 * PADH * (int)sizeof(__half);
    const size_t AGG_BYTES = (size_t)NN * HD * sizeof(__half);

    // fork: GEMM1 + aggh memset on sA; prep chain on main stream
    cudaEventRecord(ev0, 0);
    cudaStreamWaitEvent(sA, ev0, 0);
    cudaMemsetAsync(aggh_addr, 0, AGG_BYTES, sA);
    gemm_tc_kernel<<<GEMMB, 256, GSM, sA>>>(x, W1);
    cudaEventRecord(ev1, sA);

    detect_kernel<<<1, 256>>>((const unsigned int*)ei);
    zero_misc_kernel<<<ZBM, 256>>>();
    conv_deg_kernel<<<EB, 256>>>(ei);
    dinv_kernel<<<ZBM, 256>>>();
    gstart_kernel<<<ZBM, 256>>>(batch);
    norm_kernel<<<EB, 256>>>();

    // join: layer-1 edge phase
    cudaStreamWaitEvent(0, ev1, 0);
    edge_kernel<<<EDGB, 256>>>();
    node_kernel<<<NODB, 256>>>(b1);
    cudaEventRecord(ev2, 0);

    // fork: re-zero accumulator on sA while main stream runs GEMM2
    cudaStreamWaitEvent(sA, ev2, 0);
    cudaMemsetAsync(aggh_addr, 0, AGG_BYTES, sA);
    cudaEventRecord(ev3, sA);
    gemm_tc_kernel<<<GEMMB, 256, GSM>>>((const float*)h_addr, W2);

    // join: layer-2 edge phase
    cudaStreamWaitEvent(0, ev3, 0);
    edge_kernel<<<EDGB, 256>>>();
    node_kernel<<<NODB, 256>>>(b2);

    // pool
    pool_accum_kernel<<<PB, 128>>>(batch);
    pool_final_kernel<<<(GG * HD + 255) / 256, 256>>>(out);
}

// round 10
// speedup vs baseline: 1.3364x; 1.2764x over previous
#include <cuda_runtime.h>
#include <cuda_fp16.h>

#define NN 40000
#define EE 640000
#define HD 128
#define GG 64
#define PADH 136   // padded halves per smem row (conflict-free ldmatrix)

// ---------------- scratch (no allocs: __device__ globals) -------------------
__device__ __align__(16) float  g_xw  [(size_t)NN * HD];   // x@W f32
__device__ __align__(16) __half g_xwh [(size_t)NN * HD];   // x@W fp16 (gather)
__device__ __align__(16) __half g_aggh[(size_t)NN * HD];   // fp16 edge accum
__device__ __align__(16) float  g_h   [(size_t)NN * HD];   // layer output f32
__device__ __align__(16) int    g_degi[NN];
__device__ __align__(16) float  g_dinv[NN];
__device__ __align__(16) int    g_src [EE];
__device__ __align__(16) int    g_dst [EE];
__device__ __align__(16) int    g_gstart[GG + 1];
__device__ __align__(16) float  g_pool[GG * HD];
__device__ int g_is64;

__device__ __forceinline__ int IDX(const void* p, long long pos) {
    return g_is64 ? (int)((const long long*)p)[pos] : ((const int*)p)[pos];
}

// ---------------- dtype detection (reads first 32KB only) -------------------
__global__ void detect_kernel(const unsigned int* __restrict__ raw) {
    __shared__ int nz;
    if (threadIdx.x == 0) nz = 0;
    __syncthreads();
    int cnt = 0;
    for (int j = threadIdx.x; j < 4096; j += 256)
        if (raw[2 * j + 1] != 0u) cnt++;
    atomicAdd(&nz, cnt);
    __syncthreads();
    if (threadIdx.x == 0) g_is64 = (nz < 64) ? 1 : 0;
}

// ---------------- prep ------------------------------------------------------
__global__ void zero_misc_kernel() {
    int i = blockIdx.x * blockDim.x + threadIdx.x;
    if (i < NN) g_degi[i] = 0;
    if (i <= GG) g_gstart[i] = NN;
    if (i < GG * HD) g_pool[i] = 0.f;
}

// index convert + in-degree histogram (NO 64-bin graph-count atomics)
__global__ void conv_deg_kernel(const void* __restrict__ ei) {
    int i = blockIdx.x * blockDim.x + threadIdx.x;
    if (i >= EE) return;
    int s = IDX(ei, i);
    int d = IDX(ei, (long long)EE + i);
    g_src[i] = s;
    g_dst[i] = d;
    atomicAdd(&g_degi[d], 1);
}

__global__ void dinv_kernel() {
    int i = blockIdx.x * blockDim.x + threadIdx.x;
    if (i < NN) g_dinv[i] = rsqrtf((float)g_degi[i] + 1.0f);
}

// graph boundaries from sorted batch (no atomics)
__global__ void gstart_kernel(const void* __restrict__ batch) {
    int i = blockIdx.x * blockDim.x + threadIdx.x;
    if (i >= NN) return;
    int b  = IDX(batch, i);
    int bp = i ? IDX(batch, i - 1) : -1;
    for (int g = bp + 1; g <= b; g++) g_gstart[g] = i;
}

// ---------------- tensor-core GEMM: C[M,128] = A[M,128] @ W[128,128] --------
__global__ __launch_bounds__(256) void gemm_tc_kernel(const float* __restrict__ A,
                                                      const float* __restrict__ W) {
    extern __shared__ __half smh[];
    __half* As = smh;                 // [128][PADH]
    __half* Bs = smh + 128 * PADH;    // [128][PADH]  (Bs[k][n])

    int tid = threadIdx.x;
    long long mbase = (long long)blockIdx.x * 128;

#pragma unroll
    for (int i = 0; i < 16; i++) {
        int idx = i * 256 + tid;
        int row = idx >> 5, c4 = idx & 31;
        long long grow = mbase + row;
        float4 v = (grow < NN) ? ((const float4*)A)[grow * 32 + c4]
                               : make_float4(0.f, 0.f, 0.f, 0.f);
        __half2* dst = (__half2*)(As + row * PADH + c4 * 4);
        dst[0] = __floats2half2_rn(v.x, v.y);
        dst[1] = __floats2half2_rn(v.z, v.w);
    }
#pragma unroll
    for (int i = 0; i < 16; i++) {
        int idx = i * 256 + tid;
        int row = idx >> 5, c4 = idx & 31;
        float4 v = ((const float4*)W)[row * 32 + c4];
        __half2* dst = (__half2*)(Bs + row * PADH + c4 * 4);
        dst[0] = __floats2half2_rn(v.x, v.y);
        dst[1] = __floats2half2_rn(v.z, v.w);
    }
    __syncthreads();

    int wid = tid >> 5, lane = tid & 31;
    int wm = (wid & 3) * 32;
    int wn = (wid >> 2) * 64;

    float acc[2][8][4];
#pragma unroll
    for (int mt = 0; mt < 2; mt++)
#pragma unroll
        for (int nt = 0; nt < 8; nt++)
#pragma unroll
            for (int q = 0; q < 4; q++) acc[mt][nt][q] = 0.f;

#pragma unroll
    for (int kk = 0; kk < 8; kk++) {
        unsigned a[2][4];
#pragma unroll
        for (int mt = 0; mt < 2; mt++) {
            int r = lane & 15, c = (lane >> 4) * 8;
            unsigned addr = (unsigned)__cvta_generic_to_shared(
                As + (wm + mt * 16 + r) * PADH + kk * 16 + c);
            asm volatile("ldmatrix.sync.aligned.m8n8.x4.shared.b16 {%0,%1,%2,%3}, [%4];"
                         : "=r"(a[mt][0]), "=r"(a[mt][1]), "=r"(a[mt][2]), "=r"(a[mt][3])
                         : "r"(addr));
        }
        unsigned b[8][2];
#pragma unroll
        for (int nt2 = 0; nt2 < 4; nt2++) {
            int krow = kk * 16 + ((lane >> 3) & 1) * 8 + (lane & 7);
            int ncol = wn + nt2 * 16 + (lane >> 4) * 8;
            unsigned addr = (unsigned)__cvta_generic_to_shared(Bs + krow * PADH + ncol);
            asm volatile("ldmatrix.sync.aligned.m8n8.x4.trans.shared.b16 {%0,%1,%2,%3}, [%4];"
                         : "=r"(b[nt2 * 2][0]), "=r"(b[nt2 * 2][1]),
                           "=r"(b[nt2 * 2 + 1][0]), "=r"(b[nt2 * 2 + 1][1])
                         : "r"(addr));
        }
#pragma unroll
        for (int mt = 0; mt < 2; mt++)
#pragma unroll
            for (int nt = 0; nt < 8; nt++)
                asm volatile("mma.sync.aligned.m16n8k16.row.col.f32.f16.f16.f32 "
                             "{%0,%1,%2,%3}, {%4,%5,%6,%7}, {%8,%9}, {%0,%1,%2,%3};"
                             : "+f"(acc[mt][nt][0]), "+f"(acc[mt][nt][1]),
                               "+f"(acc[mt][nt][2]), "+f"(acc[mt][nt][3])
                             : "r"(a[mt][0]), "r"(a[mt][1]), "r"(a[mt][2]), "r"(a[mt][3]),
                               "r"(b[nt][0]), "r"(b[nt][1]));
    }

    int r0 = lane >> 2, cq = (lane & 3) * 2;
#pragma unroll
    for (int mt = 0; mt < 2; mt++) {
        long long rowA = mbase + wm + mt * 16 + r0;
        long long rowB = rowA + 8;
#pragma unroll
        for (int nt = 0; nt < 8; nt++) {
            int col = wn + nt * 8 + cq;
            if (rowA < NN) {
                *(float2*)&g_xw[rowA * HD + col] = make_float2(acc[mt][nt][0], acc[mt][nt][1]);
                *(__half2*)&g_xwh[rowA * HD + col] = __floats2half2_rn(acc[mt][nt][0], acc[mt][nt][1]);
            }
            if (rowB < NN) {
                *(float2*)&g_xw[rowB * HD + col] = make_float2(acc[mt][nt][2], acc[mt][nt][3]);
                *(__half2*)&g_xwh[rowB * HD + col] = __floats2half2_rn(acc[mt][nt][2], acc[mt][nt][3]);
            }
        }
    }
}

// ---------------- edge scatter: aggh[dst] += xwh[src] * dinv[s]*dinv[d] -----
__global__ __launch_bounds__(256) void edge_kernel() {
    long long t = (long long)blockIdx.x * 256 + threadIdx.x;
    int e = (int)(t >> 4);
    if (e >= EE) return;
    int sub = threadIdx.x & 15;
    int s = g_src[e];
    int d = g_dst[e];
    float nm = __ldg(&g_dinv[s]) * __ldg(&g_dinv[d]);
    uint4 v = ((const uint4*)g_xwh)[(size_t)s * 16 + sub];
    __half2* hv = (__half2*)&v;
#pragma unroll
    for (int i = 0; i < 4; i++) {
        float2 f = __half22float2(hv[i]);
        hv[i] = __floats2half2_rn(f.x * nm, f.y * nm);
    }
    __half* p = g_aggh + (size_t)d * HD + sub * 8;
    asm volatile("red.global.add.noftz.v4.f16x2 [%0], {%1,%2,%3,%4};"
                 :: "l"(p), "r"(v.x), "r"(v.y), "r"(v.z), "r"(v.w)
                 : "memory");
}

// ---------------- node epilogue: h = relu(aggh + xw*dinv^2 + b) -------------
__global__ void node_kernel(const float* __restrict__ b) {
    int i = blockIdx.x * blockDim.x + threadIdx.x;   // over NN*32 float4s
    int node = i >> 5, q = i & 31;
    float di = g_dinv[node];
    float d2 = di * di;
    uint2 av = ((const uint2*)g_aggh)[i];
    float2 a0 = __half22float2(*(__half2*)&av.x);
    float2 a1 = __half22float2(*(__half2*)&av.y);
    float4 w  = ((const float4*)g_xw)[i];
    float4 bb = ((const float4*)b)[q];
    float4 h;
    h.x = fmaxf(fmaf(w.x, d2, a0.x) + bb.x, 0.f);
    h.y = fmaxf(fmaf(w.y, d2, a0.y) + bb.y, 0.f);
    h.z = fmaxf(fmaf(w.z, d2, a1.x) + bb.z, 0.f);
    h.w = fmaxf(fmaf(w.w, d2, a1.y) + bb.w, 0.f);
    ((float4*)g_h)[i] = h;
}

// ---------------- mean pool over sorted batch (R4 shared-bin version) -------
#define POOL_BLOCKS 320
#define POOL_NODES  125          // 320 * 125 = 40000
__global__ __launch_bounds__(128) void pool_accum_kernel(const void* __restrict__ batch) {
    __shared__ float sh[GG * HD];        // 32 KB; thread t owns column t
    int t = threadIdx.x;
    for (int i = t; i < GG * HD; i += 128) sh[i] = 0.f;
    __syncthreads();
    int start = blockIdx.x * POOL_NODES;
    for (int n = start; n < start + POOL_NODES; n++) {
        int g = IDX(batch, n);
        sh[g * HD + t] += g_h[(size_t)n * HD + t];
    }
    __syncthreads();
    for (int i = t; i < GG * HD; i += 128) atomicAdd(&g_pool[i], sh[i]);
}

__global__ void pool_final_kernel(float* __restrict__ out) {
    int i = blockIdx.x * blockDim.x + threadIdx.x;
    if (i >= GG * HD) return;
    int g = i >> 7;
    float c = (float)(g_gstart[g + 1] - g_gstart[g]);
    out[i] = g_pool[i] / fmaxf(c, 1.0f);
}

// ---------------- launch -----------------------------------------------------
extern "C" void kernel_launch(void* const* d_in, const int* in_sizes, int n_in,
                              void* d_out, int out_size) {
    const float *x = 0, *W1 = 0, *b1 = 0, *W2 = 0, *b2 = 0;
    const void  *ei = 0, *batch = 0;
    for (int i = 0; i < n_in; i++) {
        long long sz = in_sizes[i];
        if      (sz == (long long)NN * HD) x = (const float*)d_in[i];
        else if (sz == 2LL * EE)           ei = d_in[i];
        else if (sz == NN)                 batch = d_in[i];
        else if (sz == HD * HD) { if (!W1) W1 = (const float*)d_in[i];
                                  else     W2 = (const float*)d_in[i]; }
        else if (sz == HD)      { if (!b1) b1 = (const float*)d_in[i];
                                  else     b2 = (const float*)d_in[i]; }
    }
    float* out = (float*)d_out;

    static cudaStream_t sA = 0;
    static cudaEvent_t ev0 = 0, ev1 = 0, ev2 = 0, ev3 = 0;
    static void* aggh_addr = 0;
    static void* h_addr = 0;
    if (!sA) {
        cudaStreamCreateWithFlags(&sA, cudaStreamNonBlocking);
        cudaEventCreateWithFlags(&ev0, cudaEventDisableTiming);
        cudaEventCreateWithFlags(&ev1, cudaEventDisableTiming);
        cudaEventCreateWithFlags(&ev2, cudaEventDisableTiming);
        cudaEventCreateWithFlags(&ev3, cudaEventDisableTiming);
        cudaGetSymbolAddress(&aggh_addr, g_aggh);
        cudaGetSymbolAddress(&h_addr, g_h);
        cudaFuncSetAttribute((const void*)gemm_tc_kernel,
                             cudaFuncAttributeMaxDynamicSharedMemorySize,
                             2 * 128 * PADH * (int)sizeof(__half));
    }

    const int ZBM   = (NN + 255) / 256;       // 157
    const int EB    = (EE + 255) / 256;       // 2500
    const int EDGB  = (EE * 16) / 256;        // 40000
    const int NODB  = (NN * 32) / 256;        // 5000
    const int GEMMB = (NN + 127) / 128;       // 313
    const int GSM   = 2 * 128 * PADH * (int)sizeof(__half);
    const size_t AGG_BYTES = (size_t)NN * HD * sizeof(__half);

    // fork: GEMM1 + aggh memset on sA; prep chain on main stream
    cudaEventRecord(ev0, 0);
    cudaStreamWaitEvent(sA, ev0, 0);
    cudaMemsetAsync(aggh_addr, 0, AGG_BYTES, sA);
    gemm_tc_kernel<<<GEMMB, 256, GSM, sA>>>(x, W1);
    cudaEventRecord(ev1, sA);

    detect_kernel<<<1, 256>>>((const unsigned int*)ei);
    zero_misc_kernel<<<ZBM, 256>>>();
    conv_deg_kernel<<<EB, 256>>>(ei);
    dinv_kernel<<<ZBM, 256>>>();
    gstart_kernel<<<ZBM, 256>>>(batch);

    // join: layer-1 edge phase
    cudaStreamWaitEvent(0, ev1, 0);
    edge_kernel<<<EDGB, 256>>>();
    node_kernel<<<NODB, 256>>>(b1);
    cudaEventRecord(ev2, 0);

    // fork: re-zero accumulator on sA while main stream runs GEMM2
    cudaStreamWaitEvent(sA, ev2, 0);
    cudaMemsetAsync(aggh_addr, 0, AGG_BYTES, sA);
    cudaEventRecord(ev3, sA);
    gemm_tc_kernel<<<GEMMB, 256, GSM>>>((const float*)h_addr, W2);

    // join: layer-2 edge phase
    cudaStreamWaitEvent(0, ev3, 0);
    edge_kernel<<<EDGB, 256>>>();
    node_kernel<<<NODB, 256>>>(b2);

    // pool
    pool_accum_kernel<<<POOL_BLOCKS, 128>>>(batch);
    pool_final_kernel<<<(GG * HD + 255) / 256, 256>>>(out);
}